// round 4
// baseline (speedup 1.0000x reference)
#include <cuda_runtime.h>

#define FULLMASK 0xFFFFFFFFu

// Fixed problem shape
#define BB 16
#define CC 67
#define HH 128
#define WW 128
#define PM 72
#define PR 9
#define NPLANE (HH * WW)            // 16384
#define NPIX ((size_t)BB * CC * NPLANE)

#define NGROUP 4                    // stream groups
#define GB (BB / NGROUP)            // 4 batches per group

// Scratch (no cudaMalloc allowed)
__device__ float g_pooled[BB * CC];
__device__ float g_kern[BB * 81];   // [b][gidx 0..8][k2 0..8]; groups 0..7 = main, 8 = remainder

// ---------------------------------------------------------------------------
// Streams/events for per-batch-group pipelining, created once at load time
// (host-side resources only; every kernel_launch call records identical work).
// ---------------------------------------------------------------------------
static cudaStream_t g_st[NGROUP];
static cudaEvent_t g_fork;
static cudaEvent_t g_join[NGROUP];
namespace {
struct StreamInit {
    StreamInit() {
        for (int i = 0; i < NGROUP; i++)
            cudaStreamCreateWithFlags(&g_st[i], cudaStreamNonBlocking);
        cudaEventCreateWithFlags(&g_fork, cudaEventDisableTiming);
        for (int i = 0; i < NGROUP; i++)
            cudaEventCreateWithFlags(&g_join[i], cudaEventDisableTiming);
    }
} s_stream_init;
}

// ---------------------------------------------------------------------------
// Kernel 1: global average pool, one block per (b,c) plane within the group
// ---------------------------------------------------------------------------
__global__ void __launch_bounds__(256) pool_kernel(const float* __restrict__ x, int b0) {
    int bc = b0 * CC + blockIdx.x;
    const float4* xp = (const float4*)(x + (size_t)bc * NPLANE);
    int tid = threadIdx.x;
    float s = 0.f;
#pragma unroll
    for (int it = 0; it < 16; it++) {
        float4 v = xp[it * 256 + tid];
        s += (v.x + v.y) + (v.z + v.w);
    }
#pragma unroll
    for (int o = 16; o; o >>= 1) s += __shfl_xor_sync(FULLMASK, s, o);
    __shared__ float ws[8];
    if ((tid & 31) == 0) ws[tid >> 5] = s;
    __syncthreads();
    if (tid == 0) {
        float t = 0.f;
#pragma unroll
        for (int i = 0; i < 8; i++) t += ws[i];
        g_pooled[bc] = t * (1.0f / (float)NPLANE);
    }
}

// ---------------------------------------------------------------------------
// Kernel 2: dynamic kernel generation. One block per batch, 128 threads.
// All weights staged in smem via coalesced loads; dots fully unrolled.
// ---------------------------------------------------------------------------
__global__ void __launch_bounds__(128) kgen_kernel(
    const float* __restrict__ w_main, const float* __restrict__ w_gate_main,
    const float* __restrict__ w_rem, const float* __restrict__ w_gate_rem,
    const float* __restrict__ bmg, const float* __restrict__ bmb,
    const float* __restrict__ bmm, const float* __restrict__ bmv,
    const float* __restrict__ brg, const float* __restrict__ brb,
    const float* __restrict__ brm, const float* __restrict__ brv, int b0) {
    int b = b0 + blockIdx.x;
    int t = threadIdx.x;

    __shared__ float s_wm[PM * CC];      // 4824
    __shared__ float s_wgm[PM * PM];     // 5184
    __shared__ float s_wr[PR * CC];      // 603
    __shared__ float s_wgr[PR * PR];     // 81
    __shared__ float sp[CC];
    __shared__ float raw[PM + PR];
    __shared__ float bn[PM + PR];

    for (int i = t; i < PM * CC; i += 128) s_wm[i] = w_main[i];
    for (int i = t; i < PM * PM; i += 128) s_wgm[i] = w_gate_main[i];
    for (int i = t; i < PR * CC; i += 128) s_wr[i] = w_rem[i];
    if (t < PR * PR) s_wgr[t] = w_gate_rem[t];
    if (t < CC) sp[t] = g_pooled[b * CC + t];
    __syncthreads();

    if (t < PM) {
        const float* wr = s_wm + t * CC;
        float s = 0.f;
#pragma unroll
        for (int c = 0; c < CC; c++) s += sp[c] * wr[c];
        raw[t] = s;
    } else if (t < PM + PR) {
        int p = t - PM;
        const float* wr = s_wr + p * CC;
        float s = 0.f;
#pragma unroll
        for (int c = 0; c < CC; c++) s += sp[c] * wr[c];
        raw[PM + p] = s;
    }
    __syncthreads();

    if (t < PM) {
        const float* wr = s_wgm + t * PM;
        float g = 0.f;
#pragma unroll
        for (int q = 0; q < PM; q++) g += raw[q] * wr[q];
        float v = raw[t] / (1.f + expf(-g));
        v = bmg[t] * (v - bmm[t]) * rsqrtf(bmv[t] + 1e-5f) + bmb[t];
        bn[t] = v;
    } else if (t < PM + PR) {
        int p = t - PM;
        const float* wr = s_wgr + p * PR;
        float g = 0.f;
#pragma unroll
        for (int q = 0; q < PR; q++) g += raw[PM + q] * wr[q];
        float v = raw[PM + p] / (1.f + expf(-g));
        v = brg[p] * (v - brm[p]) * rsqrtf(brv[p] + 1e-5f) + brb[p];
        bn[PM + p] = v;
    }
    __syncthreads();

    // 81 = 9 consecutive softmax groups of 9 (8 main groups + remainder)
    if (t < PM + PR) {
        int base = (t / 9) * 9;
        float m = -1e30f;
#pragma unroll
        for (int j = 0; j < 9; j++) m = fmaxf(m, bn[base + j]);
        float s = 0.f;
#pragma unroll
        for (int j = 0; j < 9; j++) s += expf(bn[base + j] - m);
        g_kern[b * 81 + t] = expf(bn[t] - m) / s;
    }
}

// ---------------------------------------------------------------------------
// Kernel 3: dynamic 3x3 conv (reflect pad) + residual.
// One block per (b,c,half-plane) within the group. 66x128 smem tile,
// 256 threads, streaming stores keep x L2-resident.
// ---------------------------------------------------------------------------
__global__ void __launch_bounds__(256) conv_kernel(const float* __restrict__ x,
                                                   float* __restrict__ out,
                                                   float* __restrict__ out_high,
                                                   int b0) {
    __shared__ float smem[66 * WW];
    int tile = blockIdx.x & 1;
    int lbc = blockIdx.x >> 1;
    int bc = b0 * CC + lbc;
    int b = b0 + lbc / CC, c = lbc % CC;
    int h0 = tile * 64;

    const float4* x4 = (const float4*)(x + (size_t)bc * NPLANE);
    float4* s4 = (float4*)smem;
    int tid = threadIdx.x;

    // Fill tile rows [h0-1, h0+64] with reflect at global edges
    for (int i = tid; i < 66 * 32; i += 256) {
        int r = i >> 5, col = i & 31;
        int gh = h0 - 1 + r;
        gh = gh < 0 ? -gh : (gh > HH - 1 ? 2 * (HH - 1) - gh : gh);
        s4[i] = __ldg(&x4[gh * 32 + col]);
    }

    int gidx = (c < 64) ? (c >> 3) : 8;
    const float* kp = g_kern + b * 81 + gidx * 9;
    float k0 = kp[0], k1 = kp[1], k2 = kp[2];
    float k3 = kp[3], k4 = kp[4], k5 = kp[5];
    float k6 = kp[6], k7 = kp[7], k8 = kp[8];
    __syncthreads();

    int warp = tid >> 5, lane = tid & 31;
    int lr0 = warp * 8;  // 8 local rows per warp

    float4 vp, vc, vn;
    float lp, rp, lc, rc, ln, rn;

    // load smem row sr (float4 per lane) with w-reflect halo via shuffles
#define LOADROW(sr, v, lf, rt)                                   \
    do {                                                         \
        v = s4[(sr) * 32 + lane];                                \
        lf = __shfl_up_sync(FULLMASK, v.w, 1);                   \
        if (lane == 0) lf = v.y;                                 \
        rt = __shfl_down_sync(FULLMASK, v.x, 1);                 \
        if (lane == 31) rt = v.z;                                \
    } while (0)

    LOADROW(lr0, vp, lp, rp);          // row above first output row
    LOADROW(lr0 + 1, vc, lc, rc);      // first output row

    size_t obase = (size_t)bc * NPLANE + (size_t)h0 * WW;
#pragma unroll
    for (int i = 0; i < 8; i++) {
        int lr = lr0 + i;
        LOADROW(lr + 2, vn, ln, rn);

        float4 acc;
        acc.x = k0 * lp   + k1 * vp.x + k2 * vp.y;
        acc.y = k0 * vp.x + k1 * vp.y + k2 * vp.z;
        acc.z = k0 * vp.y + k1 * vp.z + k2 * vp.w;
        acc.w = k0 * vp.z + k1 * vp.w + k2 * rp;

        acc.x += k3 * lc   + k4 * vc.x + k5 * vc.y;
        acc.y += k3 * vc.x + k4 * vc.y + k5 * vc.z;
        acc.z += k3 * vc.y + k4 * vc.z + k5 * vc.w;
        acc.w += k3 * vc.z + k4 * vc.w + k5 * rc;

        acc.x += k6 * ln   + k7 * vn.x + k8 * vn.y;
        acc.y += k6 * vn.x + k7 * vn.y + k8 * vn.z;
        acc.z += k6 * vn.y + k7 * vn.z + k8 * vn.w;
        acc.w += k6 * vn.z + k7 * vn.w + k8 * rn;

        float4 hi;
        hi.x = vc.x - acc.x;
        hi.y = vc.y - acc.y;
        hi.z = vc.z - acc.z;
        hi.w = vc.w - acc.w;

        __stcs((float4*)(out + obase + (size_t)lr * WW) + lane, acc);
        __stcs((float4*)(out_high + obase + (size_t)lr * WW) + lane, hi);

        vp = vc; lp = lc; rp = rc;
        vc = vn; lc = ln; rc = rn;
    }
#undef LOADROW
}

// ---------------------------------------------------------------------------
extern "C" void kernel_launch(void* const* d_in, const int* in_sizes, int n_in,
                              void* d_out, int out_size) {
    const float* x            = (const float*)d_in[0];
    const float* w_main       = (const float*)d_in[1];
    const float* w_gate_main  = (const float*)d_in[2];
    const float* w_rem        = (const float*)d_in[3];
    const float* w_gate_rem   = (const float*)d_in[4];
    const float* bmg          = (const float*)d_in[5];
    const float* bmb          = (const float*)d_in[6];
    const float* bmm          = (const float*)d_in[7];
    const float* bmv          = (const float*)d_in[8];
    const float* brg          = (const float*)d_in[9];
    const float* brb          = (const float*)d_in[10];
    const float* brm          = (const float*)d_in[11];
    const float* brv          = (const float*)d_in[12];

    float* out      = (float*)d_out;
    float* out_high = out + NPIX;

    // Fork: all group streams depend on the capture-origin stream
    cudaEventRecord(g_fork, 0);
    for (int g = 0; g < NGROUP; g++) {
        cudaStreamWaitEvent(g_st[g], g_fork, 0);
        int b0 = g * GB;
        pool_kernel<<<GB * CC, 256, 0, g_st[g]>>>(x, b0);
        kgen_kernel<<<GB, 128, 0, g_st[g]>>>(w_main, w_gate_main, w_rem, w_gate_rem,
                                             bmg, bmb, bmm, bmv, brg, brb, brm, brv, b0);
        conv_kernel<<<GB * CC * 2, 256, 0, g_st[g]>>>(x, out, out_high, b0);
        cudaEventRecord(g_join[g], g_st[g]);
    }
    // Join back into the capture-origin stream
    for (int g = 0; g < NGROUP; g++)
        cudaStreamWaitEvent(0, g_join[g], 0);
}

// round 5
// speedup vs baseline: 1.0622x; 1.0622x over previous
#include <cuda_runtime.h>

#define FULLMASK 0xFFFFFFFFu

// Fixed problem shape
#define BB 16
#define CC 67
#define HH 128
#define WW 128
#define PM 72
#define PR 9
#define NPLANE (HH * WW)            // 16384
#define NPIX ((size_t)BB * CC * NPLANE)

#define GRID 592                    // 4 blocks/SM x 148 SMs -- all co-resident
#define NTILE (BB * CC * 2)         // 2144 conv half-plane tiles
#define NPLANES (BB * CC)           // 1072

// Scratch (no cudaMalloc allowed)
__device__ float g_pooled[BB * CC];
__device__ float g_kern[BB * 81];
__device__ unsigned long long g_bar = 0ULL;   // monotonic -> replay-safe

// ---------------------------------------------------------------------------
// Grid-wide barrier: release-fence + relaxed atomic arrive, acquire-spin.
// Counter never resets; target derived from arrival round.
// ---------------------------------------------------------------------------
__device__ __forceinline__ void grid_barrier() {
    __syncthreads();
    if (threadIdx.x == 0) {
        __threadfence();                                      // release
        unsigned long long old = atomicAdd(&g_bar, 1ULL);
        unsigned long long target = (old / GRID + 1ULL) * GRID;
        for (;;) {
            unsigned long long v;
            asm volatile("ld.acquire.gpu.u64 %0, [%1];" : "=l"(v) : "l"(&g_bar));
            if (v >= target) break;
            __nanosleep(64);
        }
    }
    __syncthreads();
}

// ---------------------------------------------------------------------------
// One persistent kernel: pool -> barrier -> kgen -> barrier -> conv
// ---------------------------------------------------------------------------
__global__ void __launch_bounds__(256, 4) fused_kernel(
    const float* __restrict__ x,
    const float* __restrict__ w_main, const float* __restrict__ w_gate_main,
    const float* __restrict__ w_rem, const float* __restrict__ w_gate_rem,
    const float* __restrict__ bmg, const float* __restrict__ bmb,
    const float* __restrict__ bmm, const float* __restrict__ bmv,
    const float* __restrict__ brg, const float* __restrict__ brb,
    const float* __restrict__ brm, const float* __restrict__ brv,
    float* __restrict__ out, float* __restrict__ out_high) {
    __shared__ float smem[66 * WW];           // 33792 B, reused across phases
    int tid = threadIdx.x;

    // ================= Phase 1: global average pool =================
    for (int bc = blockIdx.x; bc < NPLANES; bc += GRID) {
        const float4* xp = (const float4*)(x + (size_t)bc * NPLANE);
        float s = 0.f;
#pragma unroll
        for (int it = 0; it < 16; it++) {
            float4 v = xp[it * 256 + tid];
            s += (v.x + v.y) + (v.z + v.w);
        }
#pragma unroll
        for (int o = 16; o; o >>= 1) s += __shfl_xor_sync(FULLMASK, s, o);
        if ((tid & 31) == 0) smem[tid >> 5] = s;
        __syncthreads();
        if (tid == 0) {
            float t = 0.f;
#pragma unroll
            for (int i = 0; i < 8; i++) t += smem[i];
            g_pooled[bc] = t * (1.0f / (float)NPLANE);
        }
        __syncthreads();
    }

    grid_barrier();

    // ================= Phase 2: kernel generation (blocks 0..15) ====
    if (blockIdx.x < BB) {
        int b = blockIdx.x;
        float* sp  = smem;          // 67
        float* raw = smem + 80;     // 81
        float* bn  = smem + 176;    // 81
        if (tid < CC) sp[tid] = __ldcg(&g_pooled[b * CC + tid]);
        __syncthreads();

        if (tid < PM) {
            const float* wr = w_main + tid * CC;
            float s = 0.f;
#pragma unroll
            for (int c = 0; c < CC; c++) s += sp[c] * __ldg(&wr[c]);
            raw[tid] = s;
        } else if (tid < PM + PR) {
            int p = tid - PM;
            const float* wr = w_rem + p * CC;
            float s = 0.f;
#pragma unroll
            for (int c = 0; c < CC; c++) s += sp[c] * __ldg(&wr[c]);
            raw[PM + p] = s;
        }
        __syncthreads();

        if (tid < PM) {
            const float* wr = w_gate_main + tid * PM;
            float g = 0.f;
#pragma unroll
            for (int q = 0; q < PM; q++) g += raw[q] * __ldg(&wr[q]);
            float v = raw[tid] / (1.f + expf(-g));
            v = bmg[tid] * (v - bmm[tid]) * rsqrtf(bmv[tid] + 1e-5f) + bmb[tid];
            bn[tid] = v;
        } else if (tid < PM + PR) {
            int p = tid - PM;
            const float* wr = w_gate_rem + p * PR;
            float g = 0.f;
#pragma unroll
            for (int q = 0; q < PR; q++) g += raw[PM + q] * __ldg(&wr[q]);
            float v = raw[PM + p] / (1.f + expf(-g));
            v = brg[p] * (v - brm[p]) * rsqrtf(brv[p] + 1e-5f) + brb[p];
            bn[PM + p] = v;
        }
        __syncthreads();

        if (tid < PM + PR) {
            int base = (tid / 9) * 9;
            float m = -1e30f;
#pragma unroll
            for (int j = 0; j < 9; j++) m = fmaxf(m, bn[base + j]);
            float s = 0.f;
#pragma unroll
            for (int j = 0; j < 9; j++) s += expf(bn[base + j] - m);
            g_kern[b * 81 + tid] = expf(bn[tid] - m) / s;
        }
        __syncthreads();
    }

    grid_barrier();

    // ================= Phase 3: dynamic 3x3 conv + residual =========
    int warp = tid >> 5, lane = tid & 31;
    int lr0 = warp * 8;
    float4* s4 = (float4*)smem;

    for (int tt = blockIdx.x; tt < NTILE; tt += GRID) {
        int tile = tt & 1;
        int bc = tt >> 1;
        int b = bc / CC, c = bc % CC;
        int h0 = tile * 64;

        const float4* x4 = (const float4*)(x + (size_t)bc * NPLANE);

        // Fill tile rows [h0-1, h0+64] with reflect at global edges
        for (int i = tid; i < 66 * 32; i += 256) {
            int r = i >> 5, col = i & 31;
            int gh = h0 - 1 + r;
            gh = gh < 0 ? -gh : (gh > HH - 1 ? 2 * (HH - 1) - gh : gh);
            s4[i] = __ldg(&x4[gh * 32 + col]);
        }

        int gidx = (c < 64) ? (c >> 3) : 8;
        const float* kp = g_kern + b * 81 + gidx * 9;
        float k0 = __ldcg(kp + 0), k1 = __ldcg(kp + 1), k2 = __ldcg(kp + 2);
        float k3 = __ldcg(kp + 3), k4 = __ldcg(kp + 4), k5 = __ldcg(kp + 5);
        float k6 = __ldcg(kp + 6), k7 = __ldcg(kp + 7), k8 = __ldcg(kp + 8);
        __syncthreads();

        float4 vp, vc, vn;
        float lp, rp, lc, rc, ln, rn;

#define LOADROW(sr, v, lf, rt)                                   \
    do {                                                         \
        v = s4[(sr) * 32 + lane];                                \
        lf = __shfl_up_sync(FULLMASK, v.w, 1);                   \
        if (lane == 0) lf = v.y;                                 \
        rt = __shfl_down_sync(FULLMASK, v.x, 1);                 \
        if (lane == 31) rt = v.z;                                \
    } while (0)

        LOADROW(lr0, vp, lp, rp);
        LOADROW(lr0 + 1, vc, lc, rc);

        size_t obase = (size_t)bc * NPLANE + (size_t)h0 * WW;
#pragma unroll
        for (int i = 0; i < 8; i++) {
            int lr = lr0 + i;
            LOADROW(lr + 2, vn, ln, rn);

            float4 acc;
            acc.x = k0 * lp   + k1 * vp.x + k2 * vp.y;
            acc.y = k0 * vp.x + k1 * vp.y + k2 * vp.z;
            acc.z = k0 * vp.y + k1 * vp.z + k2 * vp.w;
            acc.w = k0 * vp.z + k1 * vp.w + k2 * rp;

            acc.x += k3 * lc   + k4 * vc.x + k5 * vc.y;
            acc.y += k3 * vc.x + k4 * vc.y + k5 * vc.z;
            acc.z += k3 * vc.y + k4 * vc.z + k5 * vc.w;
            acc.w += k3 * vc.z + k4 * vc.w + k5 * rc;

            acc.x += k6 * ln   + k7 * vn.x + k8 * vn.y;
            acc.y += k6 * vn.x + k7 * vn.y + k8 * vn.z;
            acc.z += k6 * vn.y + k7 * vn.z + k8 * vn.w;
            acc.w += k6 * vn.z + k7 * vn.w + k8 * rn;

            float4 hi;
            hi.x = vc.x - acc.x;
            hi.y = vc.y - acc.y;
            hi.z = vc.z - acc.z;
            hi.w = vc.w - acc.w;

            __stcs((float4*)(out + obase + (size_t)lr * WW) + lane, acc);
            __stcs((float4*)(out_high + obase + (size_t)lr * WW) + lane, hi);

            vp = vc; lp = lc; rp = rc;
            vc = vn; lc = ln; rc = rn;
        }
#undef LOADROW
        __syncthreads();   // smem reused next tile
    }
}

// ---------------------------------------------------------------------------
extern "C" void kernel_launch(void* const* d_in, const int* in_sizes, int n_in,
                              void* d_out, int out_size) {
    const float* x            = (const float*)d_in[0];
    const float* w_main       = (const float*)d_in[1];
    const float* w_gate_main  = (const float*)d_in[2];
    const float* w_rem        = (const float*)d_in[3];
    const float* w_gate_rem   = (const float*)d_in[4];
    const float* bmg          = (const float*)d_in[5];
    const float* bmb          = (const float*)d_in[6];
    const float* bmm          = (const float*)d_in[7];
    const float* bmv          = (const float*)d_in[8];
    const float* brg          = (const float*)d_in[9];
    const float* brb          = (const float*)d_in[10];
    const float* brm          = (const float*)d_in[11];
    const float* brv          = (const float*)d_in[12];

    float* out      = (float*)d_out;
    float* out_high = out + NPIX;

    fused_kernel<<<GRID, 256>>>(x, w_main, w_gate_main, w_rem, w_gate_rem,
                                bmg, bmb, bmm, bmv, brg, brb, brm, brv,
                                out, out_high);
}

// round 6
// speedup vs baseline: 1.1994x; 1.1292x over previous
#include <cuda_runtime.h>

#define FULLMASK 0xFFFFFFFFu

// Fixed problem shape
#define BB 16
#define CC 67
#define HH 128
#define WW 128
#define PM 72
#define PR 9
#define NPLANE (HH * WW)            // 16384
#define NPIX ((size_t)BB * CC * NPLANE)

#define GRID 592                    // 4 blocks/SM x 148 SMs -- all co-resident
#define NPLANES (BB * CC)           // 1072
#define STRIP 32                    // rows per warp strip
#define NSTRIP (HH / STRIP)         // 4
#define NITEMS (NPLANES * NSTRIP)   // 4288 warp work items
#define NWARPS (GRID * 8)           // 4736

// Scratch (no cudaMalloc allowed)
__device__ float g_pooled[BB * CC];
__device__ float g_kern[BB * 81];
__device__ unsigned long long g_bar = 0ULL;   // monotonic -> replay-safe

// ---------------------------------------------------------------------------
__device__ __forceinline__ void grid_barrier() {
    __syncthreads();
    if (threadIdx.x == 0) {
        __threadfence();                                      // release
        unsigned long long old = atomicAdd(&g_bar, 1ULL);
        unsigned long long target = (old / GRID + 1ULL) * GRID;
        for (;;) {
            unsigned long long v;
            asm volatile("ld.acquire.gpu.u64 %0, [%1];" : "=l"(v) : "l"(&g_bar));
            if (v >= target) break;
            __nanosleep(64);
        }
    }
    __syncthreads();
}

__device__ __forceinline__ int refl(int h) {
    return h < 0 ? -h : (h > HH - 1 ? 2 * (HH - 1) - h : h);
}

// ---------------------------------------------------------------------------
// One persistent kernel: pool -> barrier -> kgen -> barrier -> conv
// ---------------------------------------------------------------------------
__global__ void __launch_bounds__(256, 4) fused_kernel(
    const float* __restrict__ x,
    const float* __restrict__ w_main, const float* __restrict__ w_gate_main,
    const float* __restrict__ w_rem, const float* __restrict__ w_gate_rem,
    const float* __restrict__ bmg, const float* __restrict__ bmb,
    const float* __restrict__ bmm, const float* __restrict__ bmv,
    const float* __restrict__ brg, const float* __restrict__ brb,
    const float* __restrict__ brm, const float* __restrict__ brv,
    float* __restrict__ out, float* __restrict__ out_high) {
    __shared__ float smem[240];
    int tid = threadIdx.x;

    // ================= Phase 1: global average pool =================
    for (int bc = blockIdx.x; bc < NPLANES; bc += GRID) {
        const float4* xp = (const float4*)(x + (size_t)bc * NPLANE);
        float s = 0.f;
#pragma unroll
        for (int it = 0; it < 16; it++) {
            float4 v = xp[it * 256 + tid];
            s += (v.x + v.y) + (v.z + v.w);
        }
#pragma unroll
        for (int o = 16; o; o >>= 1) s += __shfl_xor_sync(FULLMASK, s, o);
        if ((tid & 31) == 0) smem[tid >> 5] = s;
        __syncthreads();
        if (tid == 0) {
            float t = 0.f;
#pragma unroll
            for (int i = 0; i < 8; i++) t += smem[i];
            g_pooled[bc] = t * (1.0f / (float)NPLANE);
        }
        __syncthreads();
    }

    grid_barrier();

    // ================= Phase 2: kernel generation (blocks 0..15) ====
    if (blockIdx.x < BB) {
        int b = blockIdx.x;
        float* sp  = smem;          // 67
        float* raw = smem + 80;     // 81
        float* bn  = smem + 176;    // need 81 -> smem sized 240.. careful
        // NOTE: raw needs [80,161), bn needs [176,257) -> enlarge below
        (void)bn;
    }
    // separate properly-sized shared region for kgen
    {
        __shared__ float ksm[340];
        if (blockIdx.x < BB) {
            int b = blockIdx.x;
            float* sp  = ksm;           // 67
            float* raw = ksm + 80;      // 81
            float* bn  = ksm + 176;     // 81
            if (tid < CC) sp[tid] = __ldcg(&g_pooled[b * CC + tid]);
            __syncthreads();

            if (tid < PM) {
                const float* wr = w_main + tid * CC;
                float s = 0.f;
#pragma unroll
                for (int c = 0; c < CC; c++) s += sp[c] * __ldg(&wr[c]);
                raw[tid] = s;
            } else if (tid < PM + PR) {
                int p = tid - PM;
                const float* wr = w_rem + p * CC;
                float s = 0.f;
#pragma unroll
                for (int c = 0; c < CC; c++) s += sp[c] * __ldg(&wr[c]);
                raw[PM + p] = s;
            }
            __syncthreads();

            if (tid < PM) {
                const float* wr = w_gate_main + tid * PM;
                float g = 0.f;
#pragma unroll
                for (int q = 0; q < PM; q++) g += raw[q] * __ldg(&wr[q]);
                float v = raw[tid] / (1.f + expf(-g));
                v = bmg[tid] * (v - bmm[tid]) * rsqrtf(bmv[tid] + 1e-5f) + bmb[tid];
                bn[tid] = v;
            } else if (tid < PM + PR) {
                int p = tid - PM;
                const float* wr = w_gate_rem + p * PR;
                float g = 0.f;
#pragma unroll
                for (int q = 0; q < PR; q++) g += raw[PM + q] * __ldg(&wr[q]);
                float v = raw[PM + p] / (1.f + expf(-g));
                v = brg[p] * (v - brm[p]) * rsqrtf(brv[p] + 1e-5f) + brb[p];
                bn[PM + p] = v;
            }
            __syncthreads();

            if (tid < PM + PR) {
                int base = (tid / 9) * 9;
                float m = -1e30f;
#pragma unroll
                for (int j = 0; j < 9; j++) m = fmaxf(m, bn[base + j]);
                float s = 0.f;
#pragma unroll
                for (int j = 0; j < 9; j++) s += expf(bn[base + j] - m);
                g_kern[b * 81 + tid] = expf(bn[tid] - m) / s;
            }
        }
    }

    grid_barrier();

    // ================= Phase 3: warp-strip conv + residual ==========
    // Each warp: one 32-row strip of one plane. No smem, no block syncs.
    int lane = tid & 31;
    int gw = blockIdx.x * 8 + (tid >> 5);

    // halo extraction for a freshly loaded row
#define HALO(v, lf, rt)                                          \
    do {                                                         \
        lf = __shfl_up_sync(FULLMASK, v.w, 1);                   \
        if (lane == 0) lf = v.y;                                 \
        rt = __shfl_down_sync(FULLMASK, v.x, 1);                 \
        if (lane == 31) rt = v.z;                                \
    } while (0)

    for (int it = gw; it < NITEMS; it += NWARPS) {
        int bc = it >> 2;
        int r0 = (it & 3) * STRIP;
        int b = bc / CC, c = bc % CC;

        int gidx = (c < 64) ? (c >> 3) : 8;
        const float* kp = g_kern + b * 81 + gidx * 9;
        float k0 = __ldcg(kp + 0), k1 = __ldcg(kp + 1), k2 = __ldcg(kp + 2);
        float k3 = __ldcg(kp + 3), k4 = __ldcg(kp + 4), k5 = __ldcg(kp + 5);
        float k6 = __ldcg(kp + 6), k7 = __ldcg(kp + 7), k8 = __ldcg(kp + 8);

        const float* xb = x + (size_t)bc * NPLANE;
        float* ob = out + (size_t)bc * NPLANE;
        float* hb = out_high + (size_t)bc * NPLANE;

#define LDROW(h) (((const float4*)(xb + refl(h) * WW))[lane])

        float4 vA = LDROW(r0 - 1);
        float4 vB = LDROW(r0);
        float4 vC = LDROW(r0 + 1);
        float4 p1 = LDROW(r0 + 2);
        float la, ra, lb, rb, lc2, rc2, lp1, rp1;
        HALO(vA, la, ra);
        HALO(vB, lb, rb);
        HALO(vC, lc2, rc2);
        HALO(p1, lp1, rp1);

#pragma unroll 4
        for (int i = 0; i < STRIP; i++) {
            // prefetch row i+3 (depth-2 pipeline)
            float4 p2 = LDROW(r0 + i + 3);

            float4 acc;
            acc.x = k0 * la   + k1 * vA.x + k2 * vA.y;
            acc.y = k0 * vA.x + k1 * vA.y + k2 * vA.z;
            acc.z = k0 * vA.y + k1 * vA.z + k2 * vA.w;
            acc.w = k0 * vA.z + k1 * vA.w + k2 * ra;

            acc.x += k3 * lb   + k4 * vB.x + k5 * vB.y;
            acc.y += k3 * vB.x + k4 * vB.y + k5 * vB.z;
            acc.z += k3 * vB.y + k4 * vB.z + k5 * vB.w;
            acc.w += k3 * vB.z + k4 * vB.w + k5 * rb;

            acc.x += k6 * lc2   + k7 * vC.x + k8 * vC.y;
            acc.y += k6 * vC.x  + k7 * vC.y + k8 * vC.z;
            acc.z += k6 * vC.y  + k7 * vC.z + k8 * vC.w;
            acc.w += k6 * vC.z  + k7 * vC.w + k8 * rc2;

            float4 hi;
            hi.x = vB.x - acc.x;
            hi.y = vB.y - acc.y;
            hi.z = vB.z - acc.z;
            hi.w = vB.w - acc.w;

            int r = r0 + i;
            __stcs((float4*)(ob + r * WW) + lane, acc);
            __stcs((float4*)(hb + r * WW) + lane, hi);

            // roll
            vA = vB; la = lb;  ra = rb;
            vB = vC; lb = lc2; rb = rc2;
            vC = p1; lc2 = lp1; rc2 = rp1;
            p1 = p2;
            HALO(p1, lp1, rp1);
        }
#undef LDROW
    }
#undef HALO
}

// ---------------------------------------------------------------------------
extern "C" void kernel_launch(void* const* d_in, const int* in_sizes, int n_in,
                              void* d_out, int out_size) {
    const float* x            = (const float*)d_in[0];
    const float* w_main       = (const float*)d_in[1];
    const float* w_gate_main  = (const float*)d_in[2];
    const float* w_rem        = (const float*)d_in[3];
    const float* w_gate_rem   = (const float*)d_in[4];
    const float* bmg          = (const float*)d_in[5];
    const float* bmb          = (const float*)d_in[6];
    const float* bmm          = (const float*)d_in[7];
    const float* bmv          = (const float*)d_in[8];
    const float* brg          = (const float*)d_in[9];
    const float* brb          = (const float*)d_in[10];
    const float* brm          = (const float*)d_in[11];
    const float* brv          = (const float*)d_in[12];

    float* out      = (float*)d_out;
    float* out_high = out + NPIX;

    fused_kernel<<<GRID, 256>>>(x, w_main, w_gate_main, w_rem, w_gate_rem,
                                bmg, bmb, bmm, bmv, brg, brb, brm, brv,
                                out, out_high);
}